// round 1
// baseline (speedup 1.0000x reference)
#include <cuda_runtime.h>

#define BB 32
#define CC 64
#define HH 64
#define WW 64
#define EE 8
#define HWC (HH*WW)

// Scratch (device globals: no allocation allowed)
__device__ float g_S[BB * 9 * CC];   // box sums, layout [(b*9+k)*C + c], k = di*3+dj
__device__ float g_val[BB];
__device__ int   g_idx[BB];

// ---------------------------------------------------------------------------
// Kernel 1: per (b,c) compute the 9 box sums S[di,dj] = sum over the 62x62
// window starting at (di,dj). Derived from row sums minus edge elements.
// One block per (b,c), 256 threads; each thread reads 16 floats (4x float4).
// ---------------------------------------------------------------------------
__global__ __launch_bounds__(256) void region_sums_kernel(const float* __restrict__ x) {
    int bc = blockIdx.x;                      // b*CC + c
    const float* img = x + (size_t)bc * HWC;
    int tid = threadIdx.x;
    int row = tid >> 2;                       // 0..63
    int q   = tid & 3;                        // quarter of row (16 floats)

    const float4* p = (const float4*)(img + row * WW + q * 16);
    float4 v0 = p[0], v1 = p[1], v2 = p[2], v3 = p[3];
    float ps = ((v0.x + v0.y) + (v0.z + v0.w)) + ((v1.x + v1.y) + (v1.z + v1.w))
             + ((v2.x + v2.y) + (v2.z + v2.w)) + ((v3.x + v3.y) + (v3.z + v3.w));

    __shared__ float  psum[256];
    __shared__ float2 eL[64];   // x[row][0], x[row][1]
    __shared__ float2 eR[64];   // x[row][62], x[row][63]
    __shared__ float  Cv[3][64];  // Cv[dj][row] = col-range sum for row

    psum[tid] = ps;
    if (q == 0) eL[row] = make_float2(v0.x, v0.y);
    if (q == 3) eR[row] = make_float2(v3.z, v3.w);
    __syncthreads();

    if (tid < 64) {
        float R = (psum[tid*4] + psum[tid*4+1]) + (psum[tid*4+2] + psum[tid*4+3]);
        // dj=0: cols 0..61 ; dj=1: cols 1..62 ; dj=2: cols 2..63
        Cv[0][tid] = R - eR[tid].x - eR[tid].y;
        Cv[1][tid] = R - eL[tid].x - eR[tid].y;
        Cv[2][tid] = R - eL[tid].x - eL[tid].y;
    }
    __syncthreads();

    if (tid < 3) {
        int dj = tid;
        float T = 0.f;
        #pragma unroll
        for (int i = 0; i < 64; i++) T += Cv[dj][i];
        int b = bc / CC, c = bc % CC;
        // di=0: rows 0..61 ; di=1: rows 1..62 ; di=2: rows 2..63
        g_S[(b*9 + 0*3 + dj)*CC + c] = T - Cv[dj][62] - Cv[dj][63];
        g_S[(b*9 + 1*3 + dj)*CC + c] = T - Cv[dj][0]  - Cv[dj][63];
        g_S[(b*9 + 2*3 + dj)*CC + c] = T - Cv[dj][0]  - Cv[dj][1];
    }
}

// ---------------------------------------------------------------------------
// Kernel 2: gating dot products, softmax, top-1, expert_weights output.
// One block per b, 256 threads (8 warps; warp e handles expert e).
// ---------------------------------------------------------------------------
__global__ __launch_bounds__(256) void gate_kernel(const float* __restrict__ gate_w,
                                                   const float* __restrict__ gate_b,
                                                   float* __restrict__ ew_out,
                                                   int write_ew) {
    int b = blockIdx.x;
    int tid = threadIdx.x;
    __shared__ float Ssh[9 * 64];          // [k*64 + c]
    __shared__ float gat[8];

    for (int i = tid; i < 576; i += 256) Ssh[i] = g_S[b*576 + i];
    __syncthreads();

    int warp = tid >> 5, lane = tid & 31;  // warp = expert index
    float acc = 0.f;
    // gate_w layout: [e][c][k] with k = di*3+dj  (e*576 + c*9 + k)
    for (int idx = lane; idx < 576; idx += 32) {
        int c = idx / 9;
        int k = idx - c * 9;
        acc += gate_w[warp * 576 + idx] * Ssh[k * 64 + c];
    }
    #pragma unroll
    for (int o = 16; o; o >>= 1) acc += __shfl_down_sync(0xffffffffu, acc, o);
    if (lane == 0) gat[warp] = acc + gate_b[warp] * 3844.0f;  // 62*62 positions
    __syncthreads();

    if (tid == 0) {
        float m = gat[0]; int mi = 0;
        #pragma unroll
        for (int e = 1; e < 8; e++) { if (gat[e] > m) { m = gat[e]; mi = e; } }
        float s = 0.f;
        #pragma unroll
        for (int e = 0; e < 8; e++) s += expf(gat[e] - m);
        g_val[b] = 1.0f / s;
        g_idx[b] = mi;
    }
    __syncthreads();
    if (write_ew && tid < 8) {
        ew_out[b * 8 + tid] = (tid == g_idx[b]) ? g_val[b] : 0.0f;
    }
}

// ---------------------------------------------------------------------------
// Kernel 3: out[b] = val[b] * W[idx[b]] @ x[b]
// GEMM: M=64 (f), N=4096 (hw), K=64 (c). Block handles 64f x 128hw, full K.
// Thread (tf,th) computes 4 f x 8 hw register tile.
// Ws stored transposed [c][f] with XOR swizzle on low 5 bits of f to keep the
// transposed STS conflict-free; Xs stored [c][128].
// ---------------------------------------------------------------------------
__global__ __launch_bounds__(256) void moe_gemm_kernel(const float* __restrict__ x,
                                                       const float* __restrict__ expert_w,
                                                       float* __restrict__ out) {
    __shared__ float Ws[64 * 64];    // [c*64 + (f ^ (c&31))]
    __shared__ float Xs[64 * 128];   // [c*128 + j]

    int b   = blockIdx.y;
    int hw0 = blockIdx.x * 128;
    int e   = g_idx[b];
    float val = g_val[b];

    const float* Wsrc = expert_w + (size_t)e * 64 * 64;   // [f][c]
    const float* Xsrc = x + (size_t)b * CC * HWC + hw0;
    int tid = threadIdx.x;

    // Load W transposed with swizzle (coalesced global read, conflict-free STS)
    #pragma unroll
    for (int i = tid; i < 4096; i += 256) {
        int f = i >> 6, c = i & 63;
        Ws[c * 64 + (f ^ (c & 31))] = Wsrc[i];
    }
    // Load X tile: 64 rows x 128 floats
    {
        int lane = tid & 31;
        int crow = tid >> 5;   // 0..7
        #pragma unroll
        for (int pass = 0; pass < 8; pass++) {
            int c = pass * 8 + crow;
            float4 v = *(const float4*)(Xsrc + (size_t)c * HWC + lane * 4);
            *(float4*)(Xs + c * 128 + lane * 4) = v;
        }
    }
    __syncthreads();

    int tf = tid >> 4;       // 0..15
    int th = tid & 15;       // 0..15
    int f0 = tf * 4;
    int j0 = th * 8;

    float acc[4][8];
    #pragma unroll
    for (int i = 0; i < 4; i++)
        #pragma unroll
        for (int j = 0; j < 8; j++) acc[i][j] = 0.f;

    #pragma unroll 8
    for (int c = 0; c < 64; c++) {
        int sw = c & 31;
        float w0 = Ws[c * 64 + ((f0 + 0) ^ sw)];
        float w1 = Ws[c * 64 + ((f0 + 1) ^ sw)];
        float w2 = Ws[c * 64 + ((f0 + 2) ^ sw)];
        float w3 = Ws[c * 64 + ((f0 + 3) ^ sw)];
        float4 xa = *(const float4*)(Xs + c * 128 + j0);
        float4 xb = *(const float4*)(Xs + c * 128 + j0 + 4);
        float xv[8] = {xa.x, xa.y, xa.z, xa.w, xb.x, xb.y, xb.z, xb.w};
        #pragma unroll
        for (int jj = 0; jj < 8; jj++) {
            acc[0][jj] += w0 * xv[jj];
            acc[1][jj] += w1 * xv[jj];
            acc[2][jj] += w2 * xv[jj];
            acc[3][jj] += w3 * xv[jj];
        }
    }

    float* outp = out + (size_t)b * CC * HWC + hw0;
    #pragma unroll
    for (int ff = 0; ff < 4; ff++) {
        float4 r0 = make_float4(acc[ff][0]*val, acc[ff][1]*val, acc[ff][2]*val, acc[ff][3]*val);
        float4 r1 = make_float4(acc[ff][4]*val, acc[ff][5]*val, acc[ff][6]*val, acc[ff][7]*val);
        *(float4*)(outp + (size_t)(f0 + ff) * HWC + j0)     = r0;
        *(float4*)(outp + (size_t)(f0 + ff) * HWC + j0 + 4) = r1;
    }
}

// ---------------------------------------------------------------------------
extern "C" void kernel_launch(void* const* d_in, const int* in_sizes, int n_in,
                              void* d_out, int out_size) {
    // Identify inputs by element count (robust to ordering)
    const float* x = nullptr, *gate_w = nullptr, *gate_b = nullptr, *expert_w = nullptr;
    for (int i = 0; i < n_in; i++) {
        switch (in_sizes[i]) {
            case BB*CC*HH*WW: x        = (const float*)d_in[i]; break;  // 524288
            case EE*CC*3*3:   gate_w   = (const float*)d_in[i]; break;  // 4608
            case EE:          gate_b   = (const float*)d_in[i]; break;  // 8
            case EE*CC*CC:    expert_w = (const float*)d_in[i]; break;  // 32768
            default: break;
        }
    }
    float* out = (float*)d_out;
    const int main_elems = BB * CC * HH * WW;
    int write_ew = (out_size >= main_elems + BB * EE) ? 1 : 0;

    region_sums_kernel<<<BB * CC, 256>>>(x);
    gate_kernel<<<BB, 256>>>(gate_w, gate_b, out + main_elems, write_ew);
    moe_gemm_kernel<<<dim3(HWC / 128, BB), 256>>>(x, expert_w, out);
}